// round 6
// baseline (speedup 1.0000x reference)
#include <cuda_runtime.h>

// AssociatorLoss: B=32, N=32
//   one[b,i,j,k,l] = sum_m a[b,i,m,l] * a[b,j,k,m]
//   two[b,i,j,k,l] = sum_m a[b,m,k,l] * a[b,i,j,m]
//   KL = sum two * log(two/one) / B
//
// R6: lane = l layout. All SMEM reads are either 32-lane-contiguous LDS.32
// (1 crossbar cyc) or all-lane broadcasts (1 cyc) -> no transposed 4-cyc
// LDS.128, no XOR swizzle, no address ALU in the hot loop. Thread tile
// 4j x 2k over 8 phases; live regs ~85 (cap 128) -> no spills (R5 pinned
// at 128 regs with 650MB of DRAM spill traffic, fma pipe 24%).

__device__ float g_partial[1024];
__device__ int   g_count = 0;

// Accurate natural log: reduce to z in [sqrt(2)/2, sqrt(2)), atanh series.
// |abs err| ~1e-7; keeps the 33M-term KL sum far inside the 1e-3 tolerance.
__device__ __forceinline__ float acc_logf(float x) {
    int ix = __float_as_int(x);
    int t  = ix - 0x3f3504f3;
    int e  = t >> 23;
    float z = __int_as_float(ix - (t & 0xff800000));
    float f = z - 1.0f;
    float s = __fdividef(f, 2.0f + f);
    float s2 = s * s;
    float p = fmaf(s2, fmaf(s2, fmaf(s2, 0.28571429f, 0.4f), 0.66666667f), 2.0f);
    return fmaf((float)e, 0.69314718f, s * p);
}

__global__ __launch_bounds__(512, 1)
void assoc_kernel(const float* __restrict__ A, float* __restrict__ out) {
    extern __shared__ float scf[];              // 32768 floats, PLAIN layout
    float4* sc4 = reinterpret_cast<float4*>(scf);

    const int i = blockIdx.x;                   // 0..31
    const int b = blockIdx.y;                   // 0..31
    const int tid = threadIdx.x;
    const float4* ab4 = reinterpret_cast<const float4*>(A + b * 32768);

    // ---- stage a[b] (128 KB) into SMEM, plain copy, coalesced ----
    #pragma unroll
    for (int it = 0; it < 16; ++it)
        sc4[it * 512 + tid] = ab4[it * 512 + tid];
    __syncthreads();

    const int l  = tid & 31;        // lane = l  (contiguous smem dim)
    const int w  = tid >> 5;        // warp 0..15
    const int jb = (w & 7) * 4;     // 8 j-groups of 4
    const int kh = w >> 3;          // k-half (0/1)

    float kl = 0.0f;

    #pragma unroll 1
    for (int p = 0; p < 8; ++p) {               // 8 phases, 2 k each
        const int kb = kh * 16 + p * 2;

        float acc1[4][2], acc2[4][2];
        #pragma unroll
        for (int jt = 0; jt < 4; ++jt) {
            acc1[jt][0] = 0.0f; acc1[jt][1] = 0.0f;
            acc2[jt][0] = 0.0f; acc2[jt][1] = 0.0f;
        }

        #pragma unroll
        for (int mc = 0; mc < 8; ++mc) {        // m = mc*4 + mm
            // broadcast float4s over m: a[b,i,j,m*] and a[b,j,k,m*]
            float4 aj4[4], r0_4[4], r1_4[4];
            #pragma unroll
            for (int jt = 0; jt < 4; ++jt) {
                const int j = jb + jt;
                aj4[jt]  = sc4[(i * 32 + j) * 8 + mc];          // a[i,j,m..]
                r0_4[jt] = sc4[(j * 32 + kb) * 8 + mc];         // a[j,kb,m..]
                r1_4[jt] = sc4[(j * 32 + kb + 1) * 8 + mc];     // a[j,kb+1,m..]
            }

            #pragma unroll
            for (int mm = 0; mm < 4; ++mm) {
                const int m = mc * 4 + mm;
                float sm = scf[(i * 32 + m) * 32 + l];          // a[i,m,l] contig
                float v0 = scf[(m * 32 + kb) * 32 + l];         // a[m,kb,l] contig
                float v1 = scf[(m * 32 + kb + 1) * 32 + l];     // a[m,kb+1,l]

                #pragma unroll
                for (int jt = 0; jt < 4; ++jt) {
                    float ajv = ((const float*)&aj4[jt])[mm];
                    float r0  = ((const float*)&r0_4[jt])[mm];
                    float r1  = ((const float*)&r1_4[jt])[mm];
                    acc2[jt][0] = fmaf(ajv, v0, acc2[jt][0]);
                    acc2[jt][1] = fmaf(ajv, v1, acc2[jt][1]);
                    acc1[jt][0] = fmaf(r0, sm, acc1[jt][0]);
                    acc1[jt][1] = fmaf(r1, sm, acc1[jt][1]);
                }
            }
        }

        // ---- KL for this 4x2 tile: two * log(two/one) ----
        #pragma unroll
        for (int jt = 0; jt < 4; ++jt)
            #pragma unroll
            for (int kt = 0; kt < 2; ++kt) {
                float two = acc2[jt][kt];
                float one = acc1[jt][kt];
                kl = fmaf(two, acc_logf(__fdividef(two, one)), kl);
            }
    }

    // ---- deterministic block reduction ----
    #pragma unroll
    for (int o = 16; o > 0; o >>= 1)
        kl += __shfl_xor_sync(0xffffffffu, kl, o);

    __shared__ float sred[16];
    __shared__ bool  s_last;
    if ((tid & 31) == 0) sred[w] = kl;
    __syncthreads();

    if (tid == 0) {
        float s = 0.0f;
        #pragma unroll
        for (int x = 0; x < 16; ++x) s += sred[x];
        g_partial[b * 32 + i] = s;
        __threadfence();
        s_last = (atomicAdd(&g_count, 1) == 1023);
    }
    __syncthreads();

    // ---- last CTA: deterministic double-precision final reduce ----
    if (s_last && tid < 32) {
        __threadfence();
        double s = 0.0;
        #pragma unroll
        for (int it = 0; it < 32; ++it)
            s += (double)g_partial[it * 32 + tid];
        #pragma unroll
        for (int o = 16; o > 0; o >>= 1)
            s += __shfl_xor_sync(0xffffffffu, s, o);
        if (tid == 0) {
            out[0] = (float)(s * (1.0 / 32.0));   // / B
            g_count = 0;                          // reset for next graph replay
        }
    }
}

extern "C" void kernel_launch(void* const* d_in, const int* in_sizes, int n_in,
                              void* d_out, int out_size) {
    const float* A = (const float*)d_in[0];
    float* out = (float*)d_out;

    cudaFuncSetAttribute(assoc_kernel,
                         cudaFuncAttributeMaxDynamicSharedMemorySize, 131072);

    dim3 grid(32, 32);   // (i, b)
    assoc_kernel<<<grid, 512, 131072>>>(A, out);
}